// round 13
// baseline (speedup 1.0000x reference)
#include <cuda_runtime.h>
#include <cuda_fp16.h>
#include <cstdint>

#define D_F 16

// ---- global prepped weight image (fp16 hi/lo; lo halves unused) ----
// Per field d (2048 B at d*2048):
//   +0    : W1, 4 tiles 8x8 f16: [hi n0-7][hi n8-15][lo n0-7][lo n8-15]
//           row=n, col=k: k<3 -> W1[d][n][k], k==3 -> b1[d][n], else 0
//   +512  : W2, 8 tiles: hi{(n0,k0),(n0,k1),(n1,k0),(n1,k1)} then lo same; W2[d][g][h]
//   +1536 : W3, 4 tiles: [hi k0][hi k1][lo k0][lo k1]; row=o (0 pad o>=3), col=h
// b2 f32 [16][16] at 32768, b3 padded f32 [16][8] at 33792.
#define B2_OFF 32768
#define B3_OFF 33792
#define IMG_BYTES 34304

__device__ __align__(16) unsigned char g_img[IMG_BYTES];

// ============ prep kernel ============
__global__ void prep_kernel(const float* __restrict__ W1, const float* __restrict__ b1,
                            const float* __restrict__ W2, const float* __restrict__ b2,
                            const float* __restrict__ W3, const float* __restrict__ b3)
{
    int i = blockIdx.x * blockDim.x + threadIdx.x;
    unsigned short* wimg = (unsigned short*)g_img;
    if (i < 8192) {
        int d = i >> 9;
        int w = i & 511;
        int fb = d * 1024;
        float v = 0.0f;
        int hi_idx, lo_idx;
        if (w < 128) {                    // W1 (+ b1 in k=3 column)
            int s = w, tile = s >> 6, rr = (s >> 3) & 7, cc = s & 7;
            int n = tile * 8 + rr;
            if (cc < 3)       v = W1[d * 48 + n * 3 + cc];
            else if (cc == 3) v = b1[d * 16 + n];
            hi_idx = fb + s;        lo_idx = fb + 128 + s;
        } else if (w < 384) {             // W2
            int s = w - 128, tt = s >> 6, rr = (s >> 3) & 7, cc = s & 7;
            int nt = tt >> 1, kt = tt & 1;
            v = W2[d * 256 + (nt * 8 + rr) * 16 + (kt * 8 + cc)];
            hi_idx = fb + 256 + s;  lo_idx = fb + 512 + s;
        } else {                          // W3
            int s = w - 384, kt = s >> 6, rr = (s >> 3) & 7, cc = s & 7;
            v = (rr < 3) ? W3[d * 48 + rr * 16 + (kt * 8 + cc)] : 0.0f;
            hi_idx = fb + 768 + s;  lo_idx = fb + 896 + s;
        }
        __half hv = __float2half_rn(v);
        float res = v - __half2float(hv);
        __half lv = __float2half_rn(res);
        wimg[hi_idx] = reinterpret_cast<unsigned short&>(hv);
        wimg[lo_idx] = reinterpret_cast<unsigned short&>(lv);
    } else if (i < 8192 + 256) {
        int j = i - 8192;
        ((float*)(g_img + B2_OFF))[j] = b2[j];
    } else if (i < 8192 + 256 + 128) {
        int j = i - 8448;
        int d = j >> 3, o = j & 7;
        ((float*)(g_img + B3_OFF))[j] = (o < 3) ? b3[d * 3 + o] : 0.0f;
    }
}

// ============ mma / cvt helpers ============
__device__ __forceinline__ void ldsm4(unsigned& r0, unsigned& r1, unsigned& r2, unsigned& r3,
                                      unsigned a) {
    asm volatile("ldmatrix.sync.aligned.m8n8.x4.shared.b16 {%0,%1,%2,%3}, [%4];"
                 : "=r"(r0), "=r"(r1), "=r"(r2), "=r"(r3) : "r"(a));
}
__device__ __forceinline__ void ldsm2(unsigned& r0, unsigned& r1, unsigned a) {
    asm volatile("ldmatrix.sync.aligned.m8n8.x2.shared.b16 {%0,%1}, [%2];"
                 : "=r"(r0), "=r"(r1) : "r"(a));
}
// f16-accumulator m16n8k8: D,C are 2x b32 (f16x2)
__device__ __forceinline__ void mma_k8_h(unsigned d[2], unsigned a0, unsigned a1, unsigned b0,
                                         unsigned c0, unsigned c1) {
    asm volatile("mma.sync.aligned.m16n8k8.row.col.f16.f16.f16.f16 "
                 "{%0,%1}, {%2,%3}, {%4}, {%5,%6};"
                 : "=r"(d[0]), "=r"(d[1])
                 : "r"(a0), "r"(a1), "r"(b0), "r"(c0), "r"(c1));
}
// f16-accumulator m16n8k16
__device__ __forceinline__ void mma_k16_h(unsigned d[2], const unsigned a[4],
                                          unsigned b0, unsigned b1,
                                          unsigned c0, unsigned c1) {
    asm volatile("mma.sync.aligned.m16n8k16.row.col.f16.f16.f16.f16 "
                 "{%0,%1}, {%2,%3,%4,%5}, {%6,%7}, {%8,%9};"
                 : "=r"(d[0]), "=r"(d[1])
                 : "r"(a[0]), "r"(a[1]), "r"(a[2]), "r"(a[3]),
                   "r"(b0), "r"(b1), "r"(c0), "r"(c1));
}
// f32-accumulator m16n8k16 (layer 3 / final output)
__device__ __forceinline__ void mma_k16(float c[4], const unsigned a[4], unsigned b0, unsigned b1) {
    asm volatile("mma.sync.aligned.m16n8k16.row.col.f32.f16.f16.f32 "
                 "{%0,%1,%2,%3}, {%4,%5,%6,%7}, {%8,%9}, {%0,%1,%2,%3};"
                 : "+f"(c[0]), "+f"(c[1]), "+f"(c[2]), "+f"(c[3])
                 : "r"(a[0]), "r"(a[1]), "r"(a[2]), "r"(a[3]), "r"(b0), "r"(b1));
}
__device__ __forceinline__ unsigned cvt2(float v0, float v1) {
    unsigned h;
    asm("cvt.rn.f16x2.f32 %0, %1, %2;" : "=r"(h) : "f"(v1), "f"(v0));
    return h;
}
__device__ __forceinline__ unsigned relu2h(unsigned v) {
    unsigned r;
    asm("max.f16x2 %0, %1, %2;" : "=r"(r) : "r"(v), "r"(0u));
    return r;
}

// ============ main kernel: 3 point-tiles (48 points), f16 accum for l1/l2 ============
__global__ __launch_bounds__(128, 7)
void fields_mma_kernel(const float* __restrict__ x, float* __restrict__ out, int N)
{
    __shared__ __align__(16) unsigned char smem[IMG_BYTES];
    {
        const uint4* src = (const uint4*)g_img;
        uint4* dst = (uint4*)smem;
        for (int i = threadIdx.x; i < IMG_BYTES / 16; i += blockDim.x) dst[i] = src[i];
    }
    __syncthreads();

    const unsigned sbase = (unsigned)__cvta_generic_to_shared(smem);
    const float* sB2 = (const float*)(smem + B2_OFF);
    const float* sB3 = (const float*)(smem + B3_OFF);

    const int tid  = threadIdx.x;
    const int wid  = tid >> 5, lane = tid & 31;
    const int q    = lane & 3, r = lane >> 2;
    const unsigned lm_off = ((unsigned)(lane >> 3) << 7) + ((unsigned)(lane & 7) << 4);

    const int gwarp  = blockIdx.x * 4 + wid;
    const int nwarps = gridDim.x * 4;
    const int ntiles = (N + 47) / 48;            // 48 points per tile

    for (int tile = gwarp; tile < ntiles; tile += nwarps) {
        const int P = tile * 48;
        const int pA0 = P + r,      pA1 = P + r + 8;
        const int pB0 = P + r + 16, pB1 = P + r + 24;
        const int pC0 = P + r + 32, pC1 = P + r + 40;
        const bool iA0 = pA0 < N, iA1 = pA1 < N, iB0 = pB0 < N, iB1 = pB1 < N;
        const bool iC0 = pC0 < N, iC1 = pC1 < N;

        // ---- x A-fragments (single fp16): k = {x0,x1,x2,1,0,0,0,0} ----
        float a00 = 0.f, a01 = 0.f, a10 = 0.f, a11 = 0.f;
        float b00 = 0.f, b01 = 0.f, b10 = 0.f, b11 = 0.f;
        float c00 = 0.f, c01 = 0.f, c10 = 0.f, c11 = 0.f;
        if (q == 0) {
            if (iA0) { a00 = x[pA0]; a01 = x[N + pA0]; }
            if (iA1) { a10 = x[pA1]; a11 = x[N + pA1]; }
            if (iB0) { b00 = x[pB0]; b01 = x[N + pB0]; }
            if (iB1) { b10 = x[pB1]; b11 = x[N + pB1]; }
            if (iC0) { c00 = x[pC0]; c01 = x[N + pC0]; }
            if (iC1) { c10 = x[pC1]; c11 = x[N + pC1]; }
        } else if (q == 1) {
            if (iA0) { a00 = x[2 * N + pA0]; a01 = 1.0f; }
            if (iA1) { a10 = x[2 * N + pA1]; a11 = 1.0f; }
            if (iB0) { b00 = x[2 * N + pB0]; b01 = 1.0f; }
            if (iB1) { b10 = x[2 * N + pB1]; b11 = 1.0f; }
            if (iC0) { c00 = x[2 * N + pC0]; c01 = 1.0f; }
            if (iC1) { c10 = x[2 * N + pC1]; c11 = 1.0f; }
        }
        const unsigned xA0 = cvt2(a00, a01), xA1 = cvt2(a10, a11);
        const unsigned xB0 = cvt2(b00, b01), xB1 = cvt2(b10, b11);
        const unsigned xC0 = cvt2(c00, c01), xC1 = cvt2(c10, c11);

        #pragma unroll 1
        for (int d = 0; d < D_F; d++) {
            const unsigned fbase = sbase + (unsigned)(d * 2048);

            // ================= layer 1 (f16 accum; bias via x k=3 column) =========
            unsigned w1h0, w1h1;
            ldsm2(w1h0, w1h1, fbase + lm_off);
            unsigned cA0[2], cA1[2], cB0[2], cB1[2], cC0[2], cC1[2];
            mma_k8_h(cA0, xA0, xA1, w1h0, 0u, 0u);
            mma_k8_h(cB0, xB0, xB1, w1h0, 0u, 0u);
            mma_k8_h(cC0, xC0, xC1, w1h0, 0u, 0u);
            mma_k8_h(cA1, xA0, xA1, w1h1, 0u, 0u);
            mma_k8_h(cB1, xB0, xB1, w1h1, 0u, 0u);
            mma_k8_h(cC1, xC0, xC1, w1h1, 0u, 0u);

            // relu in place; C regs are already next layer's A fragments
            unsigned aA[4], aB[4], aC[4];
            aA[0] = relu2h(cA0[0]);  aA[1] = relu2h(cA0[1]);
            aA[2] = relu2h(cA1[0]);  aA[3] = relu2h(cA1[1]);
            aB[0] = relu2h(cB0[0]);  aB[1] = relu2h(cB0[1]);
            aB[2] = relu2h(cB1[0]);  aB[3] = relu2h(cB1[1]);
            aC[0] = relu2h(cC0[0]);  aC[1] = relu2h(cC0[1]);
            aC[2] = relu2h(cC1[0]);  aC[3] = relu2h(cC1[1]);

            // ================= layer 2 (f16 accum; bias packed f16x2) =============
            unsigned w2h0, w2h1, w2h2, w2h3;
            ldsm4(w2h0, w2h1, w2h2, w2h3, fbase + 512 + lm_off);
            float2 bn0 = *(const float2*)&sB2[d * 16 + 2 * q];
            float2 bn1 = *(const float2*)&sB2[d * 16 + 8 + 2 * q];
            const unsigned bh0 = cvt2(bn0.x, bn0.y);   // same for both row regs
            const unsigned bh1 = cvt2(bn1.x, bn1.y);

            unsigned eA0[2], eA1[2], eB0[2], eB1[2], eC0[2], eC1[2];
            mma_k16_h(eA0, aA, w2h0, w2h1, bh0, bh0);
            mma_k16_h(eB0, aB, w2h0, w2h1, bh0, bh0);
            mma_k16_h(eC0, aC, w2h0, w2h1, bh0, bh0);
            mma_k16_h(eA1, aA, w2h2, w2h3, bh1, bh1);
            mma_k16_h(eB1, aB, w2h2, w2h3, bh1, bh1);
            mma_k16_h(eC1, aC, w2h2, w2h3, bh1, bh1);

            unsigned gA[4], gB[4], gC[4];
            gA[0] = relu2h(eA0[0]);  gA[1] = relu2h(eA0[1]);
            gA[2] = relu2h(eA1[0]);  gA[3] = relu2h(eA1[1]);
            gB[0] = relu2h(eB0[0]);  gB[1] = relu2h(eB0[1]);
            gB[2] = relu2h(eB1[0]);  gB[3] = relu2h(eB1[1]);
            gC[0] = relu2h(eC0[0]);  gC[1] = relu2h(eC0[1]);
            gC[2] = relu2h(eC1[0]);  gC[3] = relu2h(eC1[1]);

            // ================= layer 3 (f32 accum, hi weights) ====================
            unsigned w3h0, w3h1;
            ldsm2(w3h0, w3h1, fbase + 1536 + lm_off);
            float2 b3v = *(const float2*)&sB3[d * 8 + 2 * q];
            float fA[4] = {b3v.x, b3v.y, b3v.x, b3v.y};
            float fB[4] = {b3v.x, b3v.y, b3v.x, b3v.y};
            float fC[4] = {b3v.x, b3v.y, b3v.x, b3v.y};
            mma_k16(fA, gA, w3h0, w3h1);  mma_k16(fB, gB, w3h0, w3h1);  mma_k16(fC, gC, w3h0, w3h1);

            // ---- store ----
            const int o0 = 2 * q, o1 = 2 * q + 1;
            if (o0 < 3) {
                float* rowp = out + (size_t)(d * 3 + o0) * N;
                if (iA0) rowp[pA0] = fA[0];
                if (iA1) rowp[pA1] = fA[2];
                if (iB0) rowp[pB0] = fB[0];
                if (iB1) rowp[pB1] = fB[2];
                if (iC0) rowp[pC0] = fC[0];
                if (iC1) rowp[pC1] = fC[2];
            }
            if (o1 < 3) {
                float* rowp = out + (size_t)(d * 3 + o1) * N;
                if (iA0) rowp[pA0] = fA[1];
                if (iA1) rowp[pA1] = fA[3];
                if (iB0) rowp[pB0] = fB[1];
                if (iB1) rowp[pB1] = fB[3];
                if (iC0) rowp[pC0] = fC[1];
                if (iC1) rowp[pC1] = fC[3];
            }
        }
    }
}

extern "C" void kernel_launch(void* const* d_in, const int* in_sizes, int n_in,
                              void* d_out, int out_size)
{
    const float* x  = (const float*)d_in[0];
    const float* W1 = (const float*)d_in[1];
    const float* b1 = (const float*)d_in[2];
    const float* W2 = (const float*)d_in[3];
    const float* b2 = (const float*)d_in[4];
    const float* W3 = (const float*)d_in[5];
    const float* b3 = (const float*)d_in[6];
    float* out = (float*)d_out;

    const int N = in_sizes[0] / 3;   // x is [1,3,N]

    prep_kernel<<<(8576 + 255) / 256, 256>>>(W1, b1, W2, b2, W3, b3);

    // 7 CTAs/SM x 128 threads on 152 SMs (grid-stride safe)
    fields_mma_kernel<<<1064, 128>>>(x, out, N);
}

// round 14
// speedup vs baseline: 1.1794x; 1.1794x over previous
#include <cuda_runtime.h>
#include <cuda_fp16.h>
#include <cstdint>

#define D_F 16

// ---- global prepped weight image (fp16, hi-only, COMPACT) ----
// Per field d (1024 B at d*1024):
//   +0    : W1, 2 tiles 8x8 f16 [n0-7][n8-15]; row=n, col=k: k<3 -> W1[d][n][k],
//           k==3 -> b1[d][n], else 0
//   +256  : W2, 4 tiles {(n0,k0),(n0,k1),(n1,k0),(n1,k1)}; W2[d][g][h]
//   +768  : W3, 2 tiles [k0][k1]; row=o (0 pad o>=3), col=h
// b2 f32 [16][16] at 16384, b3 padded f32 [16][8] at 17408.
#define B2_OFF 16384
#define B3_OFF 17408
#define IMG_BYTES 17920

__device__ __align__(16) unsigned char g_img[IMG_BYTES];

// ============ prep kernel ============
__global__ void prep_kernel(const float* __restrict__ W1, const float* __restrict__ b1,
                            const float* __restrict__ W2, const float* __restrict__ b2,
                            const float* __restrict__ W3, const float* __restrict__ b3)
{
    int i = blockIdx.x * blockDim.x + threadIdx.x;
    unsigned short* wimg = (unsigned short*)g_img;
    if (i < 8192) {                       // 16 fields x 512 hi entries
        int d = i >> 9;
        int w = i & 511;
        int fb = d * 512;                 // u16 base of field
        float v = 0.0f;
        if (w < 128) {                    // W1 (+ b1 in k=3 column)
            int s = w, tile = s >> 6, rr = (s >> 3) & 7, cc = s & 7;
            int n = tile * 8 + rr;
            if (cc < 3)       v = W1[d * 48 + n * 3 + cc];
            else if (cc == 3) v = b1[d * 16 + n];
        } else if (w < 384) {             // W2
            int s = w - 128, tt = s >> 6, rr = (s >> 3) & 7, cc = s & 7;
            int nt = tt >> 1, kt = tt & 1;
            v = W2[d * 256 + (nt * 8 + rr) * 16 + (kt * 8 + cc)];
        } else {                          // W3
            int s = w - 384, kt = s >> 6, rr = (s >> 3) & 7, cc = s & 7;
            v = (rr < 3) ? W3[d * 48 + rr * 16 + (kt * 8 + cc)] : 0.0f;
        }
        __half hv = __float2half_rn(v);
        wimg[fb + w] = reinterpret_cast<unsigned short&>(hv);
    } else if (i < 8192 + 256) {
        int j = i - 8192;
        ((float*)(g_img + B2_OFF))[j] = b2[j];
    } else if (i < 8192 + 256 + 128) {
        int j = i - 8448;
        int d = j >> 3, o = j & 7;
        ((float*)(g_img + B3_OFF))[j] = (o < 3) ? b3[d * 3 + o] : 0.0f;
    }
}

// ============ mma / cvt helpers ============
__device__ __forceinline__ void ldsm4(unsigned& r0, unsigned& r1, unsigned& r2, unsigned& r3,
                                      unsigned a) {
    asm volatile("ldmatrix.sync.aligned.m8n8.x4.shared.b16 {%0,%1,%2,%3}, [%4];"
                 : "=r"(r0), "=r"(r1), "=r"(r2), "=r"(r3) : "r"(a));
}
__device__ __forceinline__ void ldsm2(unsigned& r0, unsigned& r1, unsigned a) {
    asm volatile("ldmatrix.sync.aligned.m8n8.x2.shared.b16 {%0,%1}, [%2];"
                 : "=r"(r0), "=r"(r1) : "r"(a));
}
// f16-accumulator m16n8k8: D,C are 2x b32 (f16x2)
__device__ __forceinline__ void mma_k8_h(unsigned d[2], unsigned a0, unsigned a1, unsigned b0,
                                         unsigned c0, unsigned c1) {
    asm volatile("mma.sync.aligned.m16n8k8.row.col.f16.f16.f16.f16 "
                 "{%0,%1}, {%2,%3}, {%4}, {%5,%6};"
                 : "=r"(d[0]), "=r"(d[1])
                 : "r"(a0), "r"(a1), "r"(b0), "r"(c0), "r"(c1));
}
// f16-accumulator m16n8k16
__device__ __forceinline__ void mma_k16_h(unsigned d[2], const unsigned a[4],
                                          unsigned b0, unsigned b1,
                                          unsigned c0, unsigned c1) {
    asm volatile("mma.sync.aligned.m16n8k16.row.col.f16.f16.f16.f16 "
                 "{%0,%1}, {%2,%3,%4,%5}, {%6,%7}, {%8,%9};"
                 : "=r"(d[0]), "=r"(d[1])
                 : "r"(a[0]), "r"(a[1]), "r"(a[2]), "r"(a[3]),
                   "r"(b0), "r"(b1), "r"(c0), "r"(c1));
}
// f32-accumulator m16n8k16 (layer 3 / final output)
__device__ __forceinline__ void mma_k16(float c[4], const unsigned a[4], unsigned b0, unsigned b1) {
    asm volatile("mma.sync.aligned.m16n8k16.row.col.f32.f16.f16.f32 "
                 "{%0,%1,%2,%3}, {%4,%5,%6,%7}, {%8,%9}, {%0,%1,%2,%3};"
                 : "+f"(c[0]), "+f"(c[1]), "+f"(c[2]), "+f"(c[3])
                 : "r"(a[0]), "r"(a[1]), "r"(a[2]), "r"(a[3]), "r"(b0), "r"(b1));
}
__device__ __forceinline__ unsigned cvt2(float v0, float v1) {
    unsigned h;
    asm("cvt.rn.f16x2.f32 %0, %1, %2;" : "=r"(h) : "f"(v1), "f"(v0));
    return h;
}
__device__ __forceinline__ unsigned relu2h(unsigned v) {
    unsigned r;
    asm("max.f16x2 %0, %1, %2;" : "=r"(r) : "r"(v), "r"(0u));
    return r;
}

// ============ main kernel: 3 point-tiles (48 points), f16 accum l1/l2, 9 CTAs/SM ======
__global__ __launch_bounds__(128, 9)
void fields_mma_kernel(const float* __restrict__ x, float* __restrict__ out, int N)
{
    __shared__ __align__(16) unsigned char smem[IMG_BYTES];
    {
        const uint4* src = (const uint4*)g_img;
        uint4* dst = (uint4*)smem;
        for (int i = threadIdx.x; i < IMG_BYTES / 16; i += blockDim.x) dst[i] = src[i];
    }
    __syncthreads();

    const unsigned sbase = (unsigned)__cvta_generic_to_shared(smem);
    const float* sB2 = (const float*)(smem + B2_OFF);
    const float* sB3 = (const float*)(smem + B3_OFF);

    const int tid  = threadIdx.x;
    const int wid  = tid >> 5, lane = tid & 31;
    const int q    = lane & 3, r = lane >> 2;
    const unsigned lm_off = ((unsigned)(lane >> 3) << 7) + ((unsigned)(lane & 7) << 4);

    const int gwarp  = blockIdx.x * 4 + wid;
    const int nwarps = gridDim.x * 4;
    const int ntiles = (N + 47) / 48;            // 48 points per tile

    for (int tile = gwarp; tile < ntiles; tile += nwarps) {
        const int P = tile * 48;
        const int pA0 = P + r,      pA1 = P + r + 8;
        const int pB0 = P + r + 16, pB1 = P + r + 24;
        const int pC0 = P + r + 32, pC1 = P + r + 40;
        const bool iA0 = pA0 < N, iA1 = pA1 < N, iB0 = pB0 < N, iB1 = pB1 < N;
        const bool iC0 = pC0 < N, iC1 = pC1 < N;

        // ---- x A-fragments (single fp16): k = {x0,x1,x2,1,0,0,0,0} ----
        float a00 = 0.f, a01 = 0.f, a10 = 0.f, a11 = 0.f;
        float b00 = 0.f, b01 = 0.f, b10 = 0.f, b11 = 0.f;
        float c00 = 0.f, c01 = 0.f, c10 = 0.f, c11 = 0.f;
        if (q == 0) {
            if (iA0) { a00 = x[pA0]; a01 = x[N + pA0]; }
            if (iA1) { a10 = x[pA1]; a11 = x[N + pA1]; }
            if (iB0) { b00 = x[pB0]; b01 = x[N + pB0]; }
            if (iB1) { b10 = x[pB1]; b11 = x[N + pB1]; }
            if (iC0) { c00 = x[pC0]; c01 = x[N + pC0]; }
            if (iC1) { c10 = x[pC1]; c11 = x[N + pC1]; }
        } else if (q == 1) {
            if (iA0) { a00 = x[2 * N + pA0]; a01 = 1.0f; }
            if (iA1) { a10 = x[2 * N + pA1]; a11 = 1.0f; }
            if (iB0) { b00 = x[2 * N + pB0]; b01 = 1.0f; }
            if (iB1) { b10 = x[2 * N + pB1]; b11 = 1.0f; }
            if (iC0) { c00 = x[2 * N + pC0]; c01 = 1.0f; }
            if (iC1) { c10 = x[2 * N + pC1]; c11 = 1.0f; }
        }
        const unsigned xA0 = cvt2(a00, a01), xA1 = cvt2(a10, a11);
        const unsigned xB0 = cvt2(b00, b01), xB1 = cvt2(b10, b11);
        const unsigned xC0 = cvt2(c00, c01), xC1 = cvt2(c10, c11);

        #pragma unroll 1
        for (int d = 0; d < D_F; d++) {
            const unsigned fbase = sbase + (unsigned)(d * 1024);

            // ================= layer 1 (f16 accum; bias via x k=3 column) =========
            unsigned w1h0, w1h1;
            ldsm2(w1h0, w1h1, fbase + lm_off);
            unsigned cA0[2], cA1[2], cB0[2], cB1[2], cC0[2], cC1[2];
            mma_k8_h(cA0, xA0, xA1, w1h0, 0u, 0u);
            mma_k8_h(cB0, xB0, xB1, w1h0, 0u, 0u);
            mma_k8_h(cC0, xC0, xC1, w1h0, 0u, 0u);
            mma_k8_h(cA1, xA0, xA1, w1h1, 0u, 0u);
            mma_k8_h(cB1, xB0, xB1, w1h1, 0u, 0u);
            mma_k8_h(cC1, xC0, xC1, w1h1, 0u, 0u);

            // relu in place; C regs are already next layer's A fragments
            unsigned aA[4], aB[4], aC[4];
            aA[0] = relu2h(cA0[0]);  aA[1] = relu2h(cA0[1]);
            aA[2] = relu2h(cA1[0]);  aA[3] = relu2h(cA1[1]);
            aB[0] = relu2h(cB0[0]);  aB[1] = relu2h(cB0[1]);
            aB[2] = relu2h(cB1[0]);  aB[3] = relu2h(cB1[1]);
            aC[0] = relu2h(cC0[0]);  aC[1] = relu2h(cC0[1]);
            aC[2] = relu2h(cC1[0]);  aC[3] = relu2h(cC1[1]);

            // ================= layer 2 (f16 accum; bias packed f16x2) =============
            unsigned w2h0, w2h1, w2h2, w2h3;
            ldsm4(w2h0, w2h1, w2h2, w2h3, fbase + 256 + lm_off);
            float2 bn0 = *(const float2*)&sB2[d * 16 + 2 * q];
            float2 bn1 = *(const float2*)&sB2[d * 16 + 8 + 2 * q];
            const unsigned bh0 = cvt2(bn0.x, bn0.y);
            const unsigned bh1 = cvt2(bn1.x, bn1.y);

            unsigned eA0[2], eA1[2], eB0[2], eB1[2], eC0[2], eC1[2];
            mma_k16_h(eA0, aA, w2h0, w2h1, bh0, bh0);
            mma_k16_h(eB0, aB, w2h0, w2h1, bh0, bh0);
            mma_k16_h(eC0, aC, w2h0, w2h1, bh0, bh0);
            mma_k16_h(eA1, aA, w2h2, w2h3, bh1, bh1);
            mma_k16_h(eB1, aB, w2h2, w2h3, bh1, bh1);
            mma_k16_h(eC1, aC, w2h2, w2h3, bh1, bh1);

            unsigned gA[4], gB[4], gC[4];
            gA[0] = relu2h(eA0[0]);  gA[1] = relu2h(eA0[1]);
            gA[2] = relu2h(eA1[0]);  gA[3] = relu2h(eA1[1]);
            gB[0] = relu2h(eB0[0]);  gB[1] = relu2h(eB0[1]);
            gB[2] = relu2h(eB1[0]);  gB[3] = relu2h(eB1[1]);
            gC[0] = relu2h(eC0[0]);  gC[1] = relu2h(eC0[1]);
            gC[2] = relu2h(eC1[0]);  gC[3] = relu2h(eC1[1]);

            // ================= layer 3 (f32 accum) ====================
            unsigned w3h0, w3h1;
            ldsm2(w3h0, w3h1, fbase + 768 + lm_off);
            float2 b3v = *(const float2*)&sB3[d * 8 + 2 * q];
            float fA[4] = {b3v.x, b3v.y, b3v.x, b3v.y};
            float fB[4] = {b3v.x, b3v.y, b3v.x, b3v.y};
            float fC[4] = {b3v.x, b3v.y, b3v.x, b3v.y};
            mma_k16(fA, gA, w3h0, w3h1);  mma_k16(fB, gB, w3h0, w3h1);  mma_k16(fC, gC, w3h0, w3h1);

            // ---- store ----
            const int o0 = 2 * q, o1 = 2 * q + 1;
            if (o0 < 3) {
                float* rowp = out + (size_t)(d * 3 + o0) * N;
                if (iA0) rowp[pA0] = fA[0];
                if (iA1) rowp[pA1] = fA[2];
                if (iB0) rowp[pB0] = fB[0];
                if (iB1) rowp[pB1] = fB[2];
                if (iC0) rowp[pC0] = fC[0];
                if (iC1) rowp[pC1] = fC[2];
            }
            if (o1 < 3) {
                float* rowp = out + (size_t)(d * 3 + o1) * N;
                if (iA0) rowp[pA0] = fA[1];
                if (iA1) rowp[pA1] = fA[3];
                if (iB0) rowp[pB0] = fB[1];
                if (iB1) rowp[pB1] = fB[3];
                if (iC0) rowp[pC0] = fC[1];
                if (iC1) rowp[pC1] = fC[3];
            }
        }
    }
}

extern "C" void kernel_launch(void* const* d_in, const int* in_sizes, int n_in,
                              void* d_out, int out_size)
{
    const float* x  = (const float*)d_in[0];
    const float* W1 = (const float*)d_in[1];
    const float* b1 = (const float*)d_in[2];
    const float* W2 = (const float*)d_in[3];
    const float* b2 = (const float*)d_in[4];
    const float* W3 = (const float*)d_in[5];
    const float* b3 = (const float*)d_in[6];
    float* out = (float*)d_out;

    const int N = in_sizes[0] / 3;   // x is [1,3,N]

    prep_kernel<<<(8576 + 255) / 256, 256>>>(W1, b1, W2, b2, W3, b3);

    // 9 CTAs/SM x 128 threads on 152 SMs = 1368 CTAs, one clean wave
    fields_mma_kernel<<<1368, 128>>>(x, out, N);
}